// round 4
// baseline (speedup 1.0000x reference)
#include <cuda_runtime.h>
#include <cstdint>

#define S_LEN 512
#define B_SZ  64
#define HIDD  1024
#define EMBD  512
#define NCLS  32000
#define FEATD 2048
#define RNN_NCTA 128
// hsh2 dup [256k][64b] float2 = 128KB ; Wsh [256k][32j] float = 32KB ; pbuf 4*16*32 float = 8KB
#define RNN_SMEM (256 * 64 * 8 + 256 * 32 * 4 + 4 * 16 * 32 * 4)

#define FFMA2(d, a, b) asm("fma.rn.f32x2 %0, %1, %2, %0;" : "+l"(d) : "l"(a), "l"(b))
union F2U { unsigned long long u; float2 f; };

// ---- device scratch ----
__device__ float g_G[(size_t)S_LEN * B_SZ * HIDD];
__device__ float g_OUT[(size_t)S_LEN * B_SZ * HIDD];
__device__ float g_h0[B_SZ * HIDD];
__device__ float g_scores[(S_LEN - 1) * B_SZ];
__device__ float g_attn[(S_LEN - 1) * B_SZ];
__device__ float g_attout[B_SZ * HIDD];
__device__ unsigned g_bar_cnt;
__device__ volatile unsigned g_bar_gen;

__global__ void init_kernel() {
    int i = blockIdx.x * blockDim.x + threadIdx.x;
    if (i < B_SZ * HIDD) g_h0[i] = 0.f;
    if (i == 0) { g_bar_cnt = 0u; *(unsigned*)&g_bar_gen = 0u; }
}

// ---- K1: gates  G[(t*64+b)][j] = emb[X[b,t]] . W_ih[j] + b_ih[j] + b_hh[j] ----
// split into two launches over m (so rnn_kernel lands at profiled launch slot #4)
__global__ void __launch_bounds__(256) gates_kernel(const int* __restrict__ X,
                                                    const float* __restrict__ emb,
                                                    const float* __restrict__ W_ih,
                                                    const float* __restrict__ b_ih,
                                                    const float* __restrict__ b_hh,
                                                    int m_base) {
    __shared__ float2 As2[16 * 64];
    __shared__ float  Bs[16 * 68];
    __shared__ int rowidx[64];
    const int n0 = blockIdx.x * 64;
    const int m0 = (m_base + blockIdx.y) * 64;
    const int tid = threadIdx.x;

    if (tid < 64) {
        int m = m0 + tid;
        int t = m >> 6, b = m & 63;
        rowidx[tid] = X[b * S_LEN + t];
    }
    __syncthreads();

    const int tx = tid & 15, ty = tid >> 4;
    unsigned long long acc[4][2];
#pragma unroll
    for (int i = 0; i < 4; i++) { acc[i][0] = 0ull; acc[i][1] = 0ull; }

    const int lm = tid >> 2;
    const int lk = (tid & 3) * 4;

    for (int k0 = 0; k0 < EMBD; k0 += 16) {
        float4 av = *(const float4*)&emb[(size_t)rowidx[lm] * EMBD + k0 + lk];
        As2[(lk + 0) * 64 + lm] = make_float2(av.x, av.x);
        As2[(lk + 1) * 64 + lm] = make_float2(av.y, av.y);
        As2[(lk + 2) * 64 + lm] = make_float2(av.z, av.z);
        As2[(lk + 3) * 64 + lm] = make_float2(av.w, av.w);
        float4 bv = *(const float4*)&W_ih[(size_t)(n0 + lm) * EMBD + k0 + lk];
        Bs[(lk + 0) * 68 + lm] = bv.x; Bs[(lk + 1) * 68 + lm] = bv.y;
        Bs[(lk + 2) * 68 + lm] = bv.z; Bs[(lk + 3) * 68 + lm] = bv.w;
        __syncthreads();
#pragma unroll
        for (int kk = 0; kk < 16; kk++) {
            ulonglong2 a01 = *(const ulonglong2*)&As2[kk * 64 + ty * 4];
            ulonglong2 a23 = *(const ulonglong2*)&As2[kk * 64 + ty * 4 + 2];
            ulonglong2 bp  = *(const ulonglong2*)&Bs[kk * 68 + tx * 4];
            FFMA2(acc[0][0], a01.x, bp.x); FFMA2(acc[0][1], a01.x, bp.y);
            FFMA2(acc[1][0], a01.y, bp.x); FFMA2(acc[1][1], a01.y, bp.y);
            FFMA2(acc[2][0], a23.x, bp.x); FFMA2(acc[2][1], a23.x, bp.y);
            FFMA2(acc[3][0], a23.y, bp.x); FFMA2(acc[3][1], a23.y, bp.y);
        }
        __syncthreads();
    }
    float4 bi = *(const float4*)&b_ih[n0 + tx * 4];
    float4 bh = *(const float4*)&b_hh[n0 + tx * 4];
    float bias[4] = {bi.x + bh.x, bi.y + bh.y, bi.z + bh.z, bi.w + bh.w};
#pragma unroll
    for (int i = 0; i < 4; i++) {
        int m = m0 + ty * 4 + i;
        F2U p0, p1; p0.u = acc[i][0]; p1.u = acc[i][1];
        float4 o = make_float4(p0.f.x + bias[0], p0.f.y + bias[1],
                               p1.f.x + bias[2], p1.f.y + bias[3]);
        *(float4*)&g_G[(size_t)m * HIDD + n0 + tx * 4] = o;
    }
}

// ---- K2: persistent recurrence, cluster(4) DSMEM split-K reduce, 1 global barrier/step ----
__device__ __forceinline__ void grid_bar(unsigned target) {
    __threadfence();
    __syncthreads();
    if (threadIdx.x == 0) {
        unsigned a = atomicAdd(&g_bar_cnt, 1u);
        if (a == (unsigned)(RNN_NCTA - 1)) {
            atomicExch(&g_bar_cnt, 0u);
            __threadfence();
            atomicAdd((unsigned*)&g_bar_gen, 1u);
        } else {
            while (*(volatile unsigned*)&g_bar_gen < target) __nanosleep(32);
        }
        __threadfence();
    }
    __syncthreads();
}

__device__ __forceinline__ unsigned smem_u32(const void* p) {
    return (unsigned)__cvta_generic_to_shared(p);
}

__global__ void __launch_bounds__(256, 1) __cluster_dims__(4, 1, 1)
rnn_kernel(const float* __restrict__ W_hh) {
    extern __shared__ char smem_raw[];
    float2* hsh2 = (float2*)smem_raw;                              // [256k][64b] dup
    float*  Wsh  = (float*)(smem_raw + 256 * 64 * 8);              // [256k][32j]
    float*  pbuf = (float*)(smem_raw + 256 * 64 * 8 + 256 * 32 * 4); // [src4][16b][32j]

    const int tid = threadIdx.x;
    const int cta = blockIdx.x;
    const int jg = cta >> 2;     // 32 j-cols per group
    const int rank = cta & 3;    // == cluster rank == K-split index
    const int ks = rank;

    // resident W slice, k-major: Wsh[k*32+j] = W_hh[jg*32+j][ks*256+k]
    {
        int j = tid & 31;
        int kc = (tid >> 5) * 32;
        const float* wr = &W_hh[(size_t)(jg * 32 + j) * HIDD + ks * 256 + kc];
#pragma unroll
        for (int q = 0; q < 8; q++) {
            float4 wv = *(const float4*)&wr[q * 4];
            Wsh[(kc + q * 4 + 0) * 32 + j] = wv.x;
            Wsh[(kc + q * 4 + 1) * 32 + j] = wv.y;
            Wsh[(kc + q * 4 + 2) * 32 + j] = wv.z;
            Wsh[(kc + q * 4 + 3) * 32 + j] = wv.w;
        }
    }
    __syncthreads();

    // compute tile: 4 b x 1 j-pair per thread
    const int j0 = (tid & 15) * 2;    // 0..30
    const int b0 = (tid >> 4) * 4;    // 0..60 (4-aligned -> single 16-owner)
    // staging: thread stages 64 floats: batch sb, 64-k chunk skc
    const int sb = tid & 63;
    const int skc = (tid >> 6) * 64;
    // combine tile: 1 b-row x 2 j per thread, b-range = rank*16..+16
    const int bq = tid >> 4;          // 0..15
    const int j0c = (tid & 15) * 2;

    // DSMEM target: owner rank = b0>>4 holds my partials at slot [rank]
    unsigned praddr;
    {
        unsigned laddr = smem_u32(pbuf) + (unsigned)(((rank * 16 + (b0 & 15)) * 32 + j0) * 4);
        unsigned owner = (unsigned)(b0 >> 4);
        asm("mapa.shared::cluster.u32 %0, %1, %2;" : "=r"(praddr) : "r"(laddr), "r"(owner));
    }

    unsigned tgt = 0;
    for (int t = 0; t < S_LEN; ++t) {
        const float* hprev = (t == 0) ? g_h0 : (g_OUT + (size_t)(t - 1) * B_SZ * HIDD);
        // stage h slice transposed + duplicated
        {
            const float* hr = &hprev[(size_t)sb * HIDD + ks * 256 + skc];
#pragma unroll
            for (int q = 0; q < 16; q++) {
                float4 hv = __ldcg((const float4*)&hr[q * 4]);
                hsh2[(skc + q * 4 + 0) * 64 + sb] = make_float2(hv.x, hv.x);
                hsh2[(skc + q * 4 + 1) * 64 + sb] = make_float2(hv.y, hv.y);
                hsh2[(skc + q * 4 + 2) * 64 + sb] = make_float2(hv.z, hv.z);
                hsh2[(skc + q * 4 + 3) * 64 + sb] = make_float2(hv.w, hv.w);
            }
        }
        __syncthreads();

        unsigned long long acc[4];
        acc[0] = acc[1] = acc[2] = acc[3] = 0ull;
#pragma unroll 8
        for (int kk = 0; kk < 256; kk++) {
            ulonglong2 a01 = *(const ulonglong2*)&hsh2[kk * 64 + b0];
            ulonglong2 a23 = *(const ulonglong2*)&hsh2[kk * 64 + b0 + 2];
            unsigned long long wp = *(const unsigned long long*)&Wsh[kk * 32 + j0];
            FFMA2(acc[0], a01.x, wp);
            FFMA2(acc[1], a01.y, wp);
            FFMA2(acc[2], a23.x, wp);
            FFMA2(acc[3], a23.y, wp);
        }

        // push partials to owner CTA's pbuf[rank] via DSMEM (row stride 32 floats = 128B)
#pragma unroll
        for (int i = 0; i < 4; i++) {
            asm volatile("st.shared::cluster.b64 [%0], %1;"
                         :: "r"(praddr + (unsigned)(i * 128)), "l"(acc[i]) : "memory");
        }
        asm volatile("barrier.cluster.arrive.aligned;" ::: "memory");
        asm volatile("barrier.cluster.wait.aligned;" ::: "memory");

        // combine my b-range: sum 4 partials + G, tanh, write h
        {
            float2 s = make_float2(0.f, 0.f);
#pragma unroll
            for (int src = 0; src < 4; src++) {
                float2 p = *(const float2*)&pbuf[(src * 16 + bq) * 32 + j0c];
                s.x += p.x; s.y += p.y;
            }
            int b = rank * 16 + bq;
            size_t idx = (size_t)t * B_SZ * HIDD + (size_t)b * HIDD + jg * 32 + j0c;
            float2 g = __ldcg((const float2*)&g_G[idx]);
            float2 o = make_float2(tanhf(g.x + s.x), tanhf(g.y + s.y));
            __stcg((float2*)&g_OUT[idx], o);
        }
        grid_bar(++tgt);   // h(t) globally visible before anyone stages step t+1
    }
}

// ---- K3a: scores ----
__global__ void __launch_bounds__(256) scores_kernel() {
    const int s = blockIdx.x;
    const int w = threadIdx.x >> 5, lane = threadIdx.x & 31;
    const float* Pv = g_OUT + (size_t)s * B_SZ * HIDD;
    const float* Lv = g_OUT + (size_t)(S_LEN - 1) * B_SZ * HIDD;
#pragma unroll
    for (int i = 0; i < 8; i++) {
        int b = w * 8 + i;
        const float* p = Pv + (size_t)b * HIDD;
        const float* l = Lv + (size_t)b * HIDD;
        float acc = 0.f;
#pragma unroll 4
        for (int k = lane; k < HIDD; k += 32) acc += p[k] * l[k];
#pragma unroll
        for (int o = 16; o > 0; o >>= 1) acc += __shfl_down_sync(0xffffffffu, acc, o);
        if (lane == 0) g_scores[s * B_SZ + b] = acc;
    }
}

// ---- K3b: softmax over s per b ----
__global__ void __launch_bounds__(512) softmax_kernel() {
    const int b = blockIdx.x;
    const int tid = threadIdx.x;
    __shared__ float red[512];
    float v = (tid < S_LEN - 1) ? g_scores[tid * B_SZ + b] : -1e30f;
    red[tid] = v;
    __syncthreads();
    for (int s = 256; s > 0; s >>= 1) {
        if (tid < s) red[tid] = fmaxf(red[tid], red[tid + s]);
        __syncthreads();
    }
    float m = red[0];
    __syncthreads();
    float e = (tid < S_LEN - 1) ? expf(v - m) : 0.f;
    red[tid] = e;
    __syncthreads();
    for (int s = 256; s > 0; s >>= 1) {
        if (tid < s) red[tid] += red[tid + s];
        __syncthreads();
    }
    float inv = 1.f / red[0];
    if (tid < S_LEN - 1) g_attn[tid * B_SZ + b] = e * inv;
}

// ---- K3c: att_out ----
__global__ void __launch_bounds__(256) attout_kernel() {
    const int b = blockIdx.y;
    const int h = blockIdx.x * 256 + threadIdx.x;
    float acc = 0.f;
#pragma unroll 4
    for (int s = 0; s < S_LEN - 1; s++)
        acc += g_attn[s * B_SZ + b] * g_OUT[(size_t)s * B_SZ * HIDD + (size_t)b * HIDD + h];
    g_attout[b * HIDD + h] = acc;
}

// ---- K4: out[b][n] = [att_out | last] . W_out[n] + b_out[n] ----
__global__ void __launch_bounds__(256) out_gemm_kernel(const float* __restrict__ W_out,
                                                       const float* __restrict__ b_out,
                                                       float* __restrict__ out) {
    __shared__ float2 Fs2[16 * 64];
    __shared__ float  Ws[16 * 132];
    const int n0 = blockIdx.x * 128;
    const int tid = threadIdx.x;
    const int tx = tid & 31, ty = tid >> 5;
    const float* last = g_OUT + (size_t)(S_LEN - 1) * B_SZ * HIDD;

    unsigned long long acc[8][2];
#pragma unroll
    for (int i = 0; i < 8; i++) { acc[i][0] = 0ull; acc[i][1] = 0ull; }

    const int mm = tid >> 2;
    const int kq = (tid & 3) * 4;

    for (int k0 = 0; k0 < FEATD; k0 += 16) {
        int k = k0 + kq;
        const float* src = (k < HIDD) ? &g_attout[mm * HIDD + k]
                                      : &last[(size_t)mm * HIDD + (k - HIDD)];
        float4 fv = *(const float4*)src;
        Fs2[(kq + 0) * 64 + mm] = make_float2(fv.x, fv.x);
        Fs2[(kq + 1) * 64 + mm] = make_float2(fv.y, fv.y);
        Fs2[(kq + 2) * 64 + mm] = make_float2(fv.z, fv.z);
        Fs2[(kq + 3) * 64 + mm] = make_float2(fv.w, fv.w);
#pragma unroll
        for (int r = 0; r < 2; r++) {
            int f = tid + r * 256;
            int nn = f >> 2;
            int kq2 = (f & 3) * 4;
            float4 wv = *(const float4*)&W_out[(size_t)(n0 + nn) * FEATD + k0 + kq2];
            Ws[(kq2 + 0) * 132 + nn] = wv.x; Ws[(kq2 + 1) * 132 + nn] = wv.y;
            Ws[(kq2 + 2) * 132 + nn] = wv.z; Ws[(kq2 + 3) * 132 + nn] = wv.w;
        }
        __syncthreads();
#pragma unroll
        for (int kk = 0; kk < 16; kk++) {
            ulonglong2 a01 = *(const ulonglong2*)&Fs2[kk * 64 + ty * 8];
            ulonglong2 a23 = *(const ulonglong2*)&Fs2[kk * 64 + ty * 8 + 2];
            ulonglong2 a45 = *(const ulonglong2*)&Fs2[kk * 64 + ty * 8 + 4];
            ulonglong2 a67 = *(const ulonglong2*)&Fs2[kk * 64 + ty * 8 + 6];
            ulonglong2 wp  = *(const ulonglong2*)&Ws[kk * 132 + tx * 4];
            FFMA2(acc[0][0], a01.x, wp.x); FFMA2(acc[0][1], a01.x, wp.y);
            FFMA2(acc[1][0], a01.y, wp.x); FFMA2(acc[1][1], a01.y, wp.y);
            FFMA2(acc[2][0], a23.x, wp.x); FFMA2(acc[2][1], a23.x, wp.y);
            FFMA2(acc[3][0], a23.y, wp.x); FFMA2(acc[3][1], a23.y, wp.y);
            FFMA2(acc[4][0], a45.x, wp.x); FFMA2(acc[4][1], a45.x, wp.y);
            FFMA2(acc[5][0], a45.y, wp.x); FFMA2(acc[5][1], a45.y, wp.y);
            FFMA2(acc[6][0], a67.x, wp.x); FFMA2(acc[6][1], a67.x, wp.y);
            FFMA2(acc[7][0], a67.y, wp.x); FFMA2(acc[7][1], a67.y, wp.y);
        }
        __syncthreads();
    }
    float4 bo = *(const float4*)&b_out[n0 + tx * 4];
#pragma unroll
    for (int i = 0; i < 8; i++) {
        int m = ty * 8 + i;
        F2U p0, p1; p0.u = acc[i][0]; p1.u = acc[i][1];
        float4 o = make_float4(p0.f.x + bo.x, p0.f.y + bo.y,
                               p1.f.x + bo.z, p1.f.y + bo.w);
        *(float4*)&out[(size_t)m * NCLS + n0 + tx * 4] = o;
    }
}

// ---- launch ----
extern "C" void kernel_launch(void* const* d_in, const int* in_sizes, int n_in,
                              void* d_out, int out_size) {
    (void)in_sizes; (void)n_in; (void)out_size;
    const int*   X     = (const int*)d_in[0];
    const float* emb   = (const float*)d_in[1];
    const float* W_ih  = (const float*)d_in[2];
    const float* W_hh  = (const float*)d_in[3];
    const float* b_ih  = (const float*)d_in[4];
    const float* b_hh  = (const float*)d_in[5];
    const float* W_out = (const float*)d_in[6];
    const float* b_out = (const float*)d_in[7];
    float* out = (float*)d_out;

    static bool attr_set = false;
    if (!attr_set) {
        cudaFuncSetAttribute(rnn_kernel, cudaFuncAttributeMaxDynamicSharedMemorySize, RNN_SMEM);
        attr_set = true;
    }

    init_kernel<<<256, 256>>>();
    gates_kernel<<<dim3(HIDD / 64, 256), 256>>>(X, emb, W_ih, b_ih, b_hh, 0);
    gates_kernel<<<dim3(HIDD / 64, 256), 256>>>(X, emb, W_ih, b_ih, b_hh, 256);
    rnn_kernel<<<RNN_NCTA, 256, RNN_SMEM>>>(W_hh);
    scores_kernel<<<S_LEN - 1, 256>>>();
    softmax_kernel<<<B_SZ, 512>>>();
    attout_kernel<<<dim3(HIDD / 256, B_SZ), 256>>>();
    out_gemm_kernel<<<NCLS / 128, 256>>>(W_out, b_out, out);
}

// round 5
// speedup vs baseline: 1.0577x; 1.0577x over previous
#include <cuda_runtime.h>
#include <cstdint>

#define S_LEN 512
#define B_SZ  64
#define HIDD  1024
#define EMBD  512
#define NCLS  32000
#define FEATD 2048
#define RNN_NCTA 128
// hshf [256k][64b] float = 64KB ; Wsh [256k][32j] float = 32KB
#define RNN_SMEM (256 * 64 * 4 + 256 * 32 * 4)

#define FFMA2(d, a, b) asm("fma.rn.f32x2 %0, %1, %2, %0;" : "+l"(d) : "l"(a), "l"(b))
#define DUP2(d, s) asm("mov.b64 %0, {%1, %1};" : "=l"(d) : "r"(s))
union F2U { unsigned long long u; float2 f; };

// ---- device scratch ----
__device__ float g_G[(size_t)S_LEN * B_SZ * HIDD];
__device__ float g_OUT[(size_t)S_LEN * B_SZ * HIDD];
__device__ float g_P[4 * B_SZ * HIDD];
__device__ float g_h0[B_SZ * HIDD];
__device__ float g_scores[(S_LEN - 1) * B_SZ];
__device__ float g_attn[(S_LEN - 1) * B_SZ];
__device__ float g_attout[B_SZ * HIDD];
__device__ unsigned g_bar_grp[8 * 32];   // 8 counters on distinct 128B lines
__device__ unsigned g_bar_root;
__device__ volatile unsigned g_bar_gen;

__global__ void init_kernel() {
    int i = blockIdx.x * blockDim.x + threadIdx.x;
    if (i < B_SZ * HIDD) g_h0[i] = 0.f;
    if (i < 8 * 32) g_bar_grp[i] = 0u;
    if (i == 0) { g_bar_root = 0u; *(unsigned*)&g_bar_gen = 0u; }
}

// ---- K1: gates (two launches over m so rnn lands at profiled slot) ----
__global__ void __launch_bounds__(256) gates_kernel(const int* __restrict__ X,
                                                    const float* __restrict__ emb,
                                                    const float* __restrict__ W_ih,
                                                    const float* __restrict__ b_ih,
                                                    const float* __restrict__ b_hh,
                                                    int m_base) {
    __shared__ float2 As2[16 * 64];
    __shared__ float  Bs[16 * 68];
    __shared__ int rowidx[64];
    const int n0 = blockIdx.x * 64;
    const int m0 = (m_base + blockIdx.y) * 64;
    const int tid = threadIdx.x;

    if (tid < 64) {
        int m = m0 + tid;
        int t = m >> 6, b = m & 63;
        rowidx[tid] = X[b * S_LEN + t];
    }
    __syncthreads();

    const int tx = tid & 15, ty = tid >> 4;
    unsigned long long acc[4][2];
#pragma unroll
    for (int i = 0; i < 4; i++) { acc[i][0] = 0ull; acc[i][1] = 0ull; }

    const int lm = tid >> 2;
    const int lk = (tid & 3) * 4;

    for (int k0 = 0; k0 < EMBD; k0 += 16) {
        float4 av = *(const float4*)&emb[(size_t)rowidx[lm] * EMBD + k0 + lk];
        As2[(lk + 0) * 64 + lm] = make_float2(av.x, av.x);
        As2[(lk + 1) * 64 + lm] = make_float2(av.y, av.y);
        As2[(lk + 2) * 64 + lm] = make_float2(av.z, av.z);
        As2[(lk + 3) * 64 + lm] = make_float2(av.w, av.w);
        float4 bv = *(const float4*)&W_ih[(size_t)(n0 + lm) * EMBD + k0 + lk];
        Bs[(lk + 0) * 68 + lm] = bv.x; Bs[(lk + 1) * 68 + lm] = bv.y;
        Bs[(lk + 2) * 68 + lm] = bv.z; Bs[(lk + 3) * 68 + lm] = bv.w;
        __syncthreads();
#pragma unroll
        for (int kk = 0; kk < 16; kk++) {
            ulonglong2 a01 = *(const ulonglong2*)&As2[kk * 64 + ty * 4];
            ulonglong2 a23 = *(const ulonglong2*)&As2[kk * 64 + ty * 4 + 2];
            ulonglong2 bp  = *(const ulonglong2*)&Bs[kk * 68 + tx * 4];
            FFMA2(acc[0][0], a01.x, bp.x); FFMA2(acc[0][1], a01.x, bp.y);
            FFMA2(acc[1][0], a01.y, bp.x); FFMA2(acc[1][1], a01.y, bp.y);
            FFMA2(acc[2][0], a23.x, bp.x); FFMA2(acc[2][1], a23.x, bp.y);
            FFMA2(acc[3][0], a23.y, bp.x); FFMA2(acc[3][1], a23.y, bp.y);
        }
        __syncthreads();
    }
    float4 bi = *(const float4*)&b_ih[n0 + tx * 4];
    float4 bh = *(const float4*)&b_hh[n0 + tx * 4];
    float bias[4] = {bi.x + bh.x, bi.y + bh.y, bi.z + bh.z, bi.w + bh.w};
#pragma unroll
    for (int i = 0; i < 4; i++) {
        int m = m0 + ty * 4 + i;
        F2U p0, p1; p0.u = acc[i][0]; p1.u = acc[i][1];
        float4 o = make_float4(p0.f.x + bias[0], p0.f.y + bias[1],
                               p1.f.x + bias[2], p1.f.y + bias[3]);
        *(float4*)&g_G[(size_t)m * HIDD + n0 + tx * 4] = o;
    }
}

// ---- tree grid barrier: 8 parallel arrive lines + root ----
__device__ __forceinline__ void grid_bar(unsigned target, int cta) {
    __threadfence();
    __syncthreads();
    if (threadIdx.x == 0) {
        unsigned grp = (unsigned)(cta & 7);
        unsigned a = atomicAdd(&g_bar_grp[grp * 32], 1u);
        if (a == 15u) {
            unsigned r = atomicAdd(&g_bar_root, 1u);
            if (r == 7u) {
                g_bar_root = 0u;
#pragma unroll
                for (int g = 0; g < 8; g++) g_bar_grp[g * 32] = 0u;
                __threadfence();
                atomicAdd((unsigned*)&g_bar_gen, 1u);
            }
        }
        while (*(volatile unsigned*)&g_bar_gen < target) __nanosleep(16);
        __threadfence();
    }
    __syncthreads();
}

// ---- K2: persistent recurrence (128 CTAs x 128 thr), b-packed FFMA2, reg-dup W ----
__global__ void __launch_bounds__(128, 1) rnn_kernel(const float* __restrict__ W_hh) {
    extern __shared__ char smem_raw[];
    float* hshf = (float*)smem_raw;                      // [256k][64b] natural
    float* Wsh  = (float*)(smem_raw + 256 * 64 * 4);     // [256k][32j]
    const int tid = threadIdx.x;
    const int c = blockIdx.x;
    const int jg = c & 31;   // 32 j-cols per group
    const int ks = c >> 5;   // 256 K each

    // resident W slice, k-major: Wsh[k*32+j] = W_hh[jg*32+j][ks*256+k]
    {
        int j = tid & 31;
        int kc = (tid >> 5) * 64;
        const float* wr = &W_hh[(size_t)(jg * 32 + j) * HIDD + ks * 256 + kc];
#pragma unroll
        for (int q = 0; q < 16; q++) {
            float4 wv = *(const float4*)&wr[q * 4];
            Wsh[(kc + q * 4 + 0) * 32 + j] = wv.x;
            Wsh[(kc + q * 4 + 1) * 32 + j] = wv.y;
            Wsh[(kc + q * 4 + 2) * 32 + j] = wv.z;
            Wsh[(kc + q * 4 + 3) * 32 + j] = wv.w;
        }
    }
    __syncthreads();

    const int j0 = (tid & 7) * 4;    // 0..28
    const int b0 = (tid >> 3) * 4;   // 0..60
    const int sb = tid & 63;         // staging batch
    const int skc = (tid >> 6) * 128;
    unsigned tgt = 0;

    for (int t = 0; t < S_LEN; ++t) {
        const float* hprev = (t == 0) ? g_h0 : (g_OUT + (size_t)(t - 1) * B_SZ * HIDD);
        // stage h transposed, unduplicated: hshf[k*64+b] = h[b][k]
        {
            const float* hr = &hprev[(size_t)sb * HIDD + ks * 256 + skc];
#pragma unroll
            for (int q = 0; q < 32; q++) {
                float4 hv = __ldcg((const float4*)&hr[q * 4]);
                hshf[(skc + q * 4 + 0) * 64 + sb] = hv.x;
                hshf[(skc + q * 4 + 1) * 64 + sb] = hv.y;
                hshf[(skc + q * 4 + 2) * 64 + sb] = hv.z;
                hshf[(skc + q * 4 + 3) * 64 + sb] = hv.w;
            }
        }
        __syncthreads();

        unsigned long long acc[4][2];   // acc[j][bp]: packed over (b,b+1)
#pragma unroll
        for (int i = 0; i < 4; i++) { acc[i][0] = 0ull; acc[i][1] = 0ull; }

#pragma unroll 8
        for (int kk = 0; kk < 256; kk++) {
            ulonglong2 hp = *(const ulonglong2*)&hshf[kk * 64 + b0]; // (h0,h1),(h2,h3)
            float4 wv = *(const float4*)&Wsh[kk * 32 + j0];
            unsigned long long w0, w1, w2, w3;
            DUP2(w0, __float_as_uint(wv.x));
            DUP2(w1, __float_as_uint(wv.y));
            DUP2(w2, __float_as_uint(wv.z));
            DUP2(w3, __float_as_uint(wv.w));
            FFMA2(acc[0][0], hp.x, w0); FFMA2(acc[0][1], hp.y, w0);
            FFMA2(acc[1][0], hp.x, w1); FFMA2(acc[1][1], hp.y, w1);
            FFMA2(acc[2][0], hp.x, w2); FFMA2(acc[2][1], hp.y, w2);
            FFMA2(acc[3][0], hp.x, w3); FFMA2(acc[3][1], hp.y, w3);
        }

        // write partials: g_P[ks][b][jglobal]
#pragma unroll
        for (int p = 0; p < 2; p++) {
            F2U a0, a1, a2, a3;
            a0.u = acc[0][p]; a1.u = acc[1][p]; a2.u = acc[2][p]; a3.u = acc[3][p];
            float4 lo = make_float4(a0.f.x, a1.f.x, a2.f.x, a3.f.x);
            float4 hi = make_float4(a0.f.y, a1.f.y, a2.f.y, a3.f.y);
            *(float4*)&g_P[ks * (B_SZ * HIDD) + (b0 + 2 * p) * HIDD + jg * 32 + j0] = lo;
            *(float4*)&g_P[ks * (B_SZ * HIDD) + (b0 + 2 * p + 1) * HIDD + jg * 32 + j0] = hi;
        }
        grid_bar(++tgt, c);

        // combine 512 contiguous elements per CTA
        {
            int base = c * 512 + tid * 4;
            float4 p0 = __ldcg((const float4*)&g_P[0 * (B_SZ * HIDD) + base]);
            float4 p1 = __ldcg((const float4*)&g_P[1 * (B_SZ * HIDD) + base]);
            float4 p2 = __ldcg((const float4*)&g_P[2 * (B_SZ * HIDD) + base]);
            float4 p3 = __ldcg((const float4*)&g_P[3 * (B_SZ * HIDD) + base]);
            float4 g  = __ldcg((const float4*)&g_G[(size_t)t * B_SZ * HIDD + base]);
            float4 o;
            o.x = tanhf(g.x + p0.x + p1.x + p2.x + p3.x);
            o.y = tanhf(g.y + p0.y + p1.y + p2.y + p3.y);
            o.z = tanhf(g.z + p0.z + p1.z + p2.z + p3.z);
            o.w = tanhf(g.w + p0.w + p1.w + p2.w + p3.w);
            *(float4*)&g_OUT[(size_t)t * B_SZ * HIDD + base] = o;
        }
        grid_bar(++tgt, c);
    }
}

// ---- K3a: scores ----
__global__ void __launch_bounds__(256) scores_kernel() {
    const int s = blockIdx.x;
    const int w = threadIdx.x >> 5, lane = threadIdx.x & 31;
    const float* Pv = g_OUT + (size_t)s * B_SZ * HIDD;
    const float* Lv = g_OUT + (size_t)(S_LEN - 1) * B_SZ * HIDD;
#pragma unroll
    for (int i = 0; i < 8; i++) {
        int b = w * 8 + i;
        const float* p = Pv + (size_t)b * HIDD;
        const float* l = Lv + (size_t)b * HIDD;
        float acc = 0.f;
#pragma unroll 4
        for (int k = lane; k < HIDD; k += 32) acc += p[k] * l[k];
#pragma unroll
        for (int o = 16; o > 0; o >>= 1) acc += __shfl_down_sync(0xffffffffu, acc, o);
        if (lane == 0) g_scores[s * B_SZ + b] = acc;
    }
}

// ---- K3b: softmax over s per b ----
__global__ void __launch_bounds__(512) softmax_kernel() {
    const int b = blockIdx.x;
    const int tid = threadIdx.x;
    __shared__ float red[512];
    float v = (tid < S_LEN - 1) ? g_scores[tid * B_SZ + b] : -1e30f;
    red[tid] = v;
    __syncthreads();
    for (int s = 256; s > 0; s >>= 1) {
        if (tid < s) red[tid] = fmaxf(red[tid], red[tid + s]);
        __syncthreads();
    }
    float m = red[0];
    __syncthreads();
    float e = (tid < S_LEN - 1) ? expf(v - m) : 0.f;
    red[tid] = e;
    __syncthreads();
    for (int s = 256; s > 0; s >>= 1) {
        if (tid < s) red[tid] += red[tid + s];
        __syncthreads();
    }
    float inv = 1.f / red[0];
    if (tid < S_LEN - 1) g_attn[tid * B_SZ + b] = e * inv;
}

// ---- K3c: att_out ----
__global__ void __launch_bounds__(256) attout_kernel() {
    const int b = blockIdx.y;
    const int h = blockIdx.x * 256 + threadIdx.x;
    float acc = 0.f;
#pragma unroll 4
    for (int s = 0; s < S_LEN - 1; s++)
        acc += g_attn[s * B_SZ + b] * g_OUT[(size_t)s * B_SZ * HIDD + (size_t)b * HIDD + h];
    g_attout[b * HIDD + h] = acc;
}

// ---- K4: out GEMM ----
__global__ void __launch_bounds__(256) out_gemm_kernel(const float* __restrict__ W_out,
                                                       const float* __restrict__ b_out,
                                                       float* __restrict__ out) {
    __shared__ float2 Fs2[16 * 64];
    __shared__ float  Ws[16 * 132];
    const int n0 = blockIdx.x * 128;
    const int tid = threadIdx.x;
    const int tx = tid & 31, ty = tid >> 5;
    const float* last = g_OUT + (size_t)(S_LEN - 1) * B_SZ * HIDD;

    unsigned long long acc[8][2];
#pragma unroll
    for (int i = 0; i < 8; i++) { acc[i][0] = 0ull; acc[i][1] = 0ull; }

    const int mm = tid >> 2;
    const int kq = (tid & 3) * 4;

    for (int k0 = 0; k0 < FEATD; k0 += 16) {
        int k = k0 + kq;
        const float* src = (k < HIDD) ? &g_attout[mm * HIDD + k]
                                      : &last[(size_t)mm * HIDD + (k - HIDD)];
        float4 fv = *(const float4*)src;
        Fs2[(kq + 0) * 64 + mm] = make_float2(fv.x, fv.x);
        Fs2[(kq + 1) * 64 + mm] = make_float2(fv.y, fv.y);
        Fs2[(kq + 2) * 64 + mm] = make_float2(fv.z, fv.z);
        Fs2[(kq + 3) * 64 + mm] = make_float2(fv.w, fv.w);
#pragma unroll
        for (int r = 0; r < 2; r++) {
            int f = tid + r * 256;
            int nn = f >> 2;
            int kq2 = (f & 3) * 4;
            float4 wv = *(const float4*)&W_out[(size_t)(n0 + nn) * FEATD + k0 + kq2];
            Ws[(kq2 + 0) * 132 + nn] = wv.x; Ws[(kq2 + 1) * 132 + nn] = wv.y;
            Ws[(kq2 + 2) * 132 + nn] = wv.z; Ws[(kq2 + 3) * 132 + nn] = wv.w;
        }
        __syncthreads();
#pragma unroll
        for (int kk = 0; kk < 16; kk++) {
            ulonglong2 a01 = *(const ulonglong2*)&Fs2[kk * 64 + ty * 8];
            ulonglong2 a23 = *(const ulonglong2*)&Fs2[kk * 64 + ty * 8 + 2];
            ulonglong2 a45 = *(const ulonglong2*)&Fs2[kk * 64 + ty * 8 + 4];
            ulonglong2 a67 = *(const ulonglong2*)&Fs2[kk * 64 + ty * 8 + 6];
            ulonglong2 wp  = *(const ulonglong2*)&Ws[kk * 132 + tx * 4];
            FFMA2(acc[0][0], a01.x, wp.x); FFMA2(acc[0][1], a01.x, wp.y);
            FFMA2(acc[1][0], a01.y, wp.x); FFMA2(acc[1][1], a01.y, wp.y);
            FFMA2(acc[2][0], a23.x, wp.x); FFMA2(acc[2][1], a23.x, wp.y);
            FFMA2(acc[3][0], a23.y, wp.x); FFMA2(acc[3][1], a23.y, wp.y);
            FFMA2(acc[4][0], a45.x, wp.x); FFMA2(acc[4][1], a45.x, wp.y);
            FFMA2(acc[5][0], a45.y, wp.x); FFMA2(acc[5][1], a45.y, wp.y);
            FFMA2(acc[6][0], a67.x, wp.x); FFMA2(acc[6][1], a67.x, wp.y);
            FFMA2(acc[7][0], a67.y, wp.x); FFMA2(acc[7][1], a67.y, wp.y);
        }
        __syncthreads();
    }
    float4 bo = *(const float4*)&b_out[n0 + tx * 4];
#pragma unroll
    for (int i = 0; i < 8; i++) {
        int m = ty * 8 + i;
        F2U p0, p1; p0.u = acc[i][0]; p1.u = acc[i][1];
        float4 o = make_float4(p0.f.x + bo.x, p0.f.y + bo.y,
                               p1.f.x + bo.z, p1.f.y + bo.w);
        *(float4*)&out[(size_t)m * NCLS + n0 + tx * 4] = o;
    }
}

// ---- launch ----
extern "C" void kernel_launch(void* const* d_in, const int* in_sizes, int n_in,
                              void* d_out, int out_size) {
    (void)in_sizes; (void)n_in; (void)out_size;
    const int*   X     = (const int*)d_in[0];
    const float* emb   = (const float*)d_in[1];
    const float* W_ih  = (const float*)d_in[2];
    const float* W_hh  = (const float*)d_in[3];
    const float* b_ih  = (const float*)d_in[4];
    const float* b_hh  = (const float*)d_in[5];
    const float* W_out = (const float*)d_in[6];
    const float* b_out = (const float*)d_in[7];
    float* out = (float*)d_out;

    static bool attr_set = false;
    if (!attr_set) {
        cudaFuncSetAttribute(rnn_kernel, cudaFuncAttributeMaxDynamicSharedMemorySize, RNN_SMEM);
        attr_set = true;
    }

    init_kernel<<<256, 256>>>();
    gates_kernel<<<dim3(HIDD / 64, 256), 256>>>(X, emb, W_ih, b_ih, b_hh, 0);
    gates_kernel<<<dim3(HIDD / 64, 256), 256>>>(X, emb, W_ih, b_ih, b_hh, 256);
    rnn_kernel<<<RNN_NCTA, 128, RNN_SMEM>>>(W_hh);
    scores_kernel<<<S_LEN - 1, 256>>>();
    softmax_kernel<<<B_SZ, 512>>>();
    attout_kernel<<<dim3(HIDD / 256, B_SZ), 256>>>();
    out_gemm_kernel<<<NCLS / 128, 256>>>(W_out, b_out, out);
}

// round 6
// speedup vs baseline: 1.5354x; 1.4516x over previous
#include <cuda_runtime.h>
#include <cstdint>

#define S_LEN 512
#define B_SZ  64
#define HIDD  1024
#define EMBD  512
#define NCLS  32000
#define FEATD 2048
#define RNN_NCTA 128
#define RNN_KS 8
// hshf [128k][64b] float = 32KB ; Wd dup [128k][128] float = 64KB
#define RNN_SMEM (128 * 64 * 4 + 128 * 128 * 4)

#define FFMA2(d, a, b) asm("fma.rn.f32x2 %0, %1, %2, %0;" : "+l"(d) : "l"(a), "l"(b))
union F2U { unsigned long long u; float2 f; };

// ---- device scratch ----
__device__ float g_G[(size_t)S_LEN * B_SZ * HIDD];
__device__ float g_OUT[(size_t)S_LEN * B_SZ * HIDD];
__device__ float g_P[RNN_KS * B_SZ * HIDD];
__device__ float g_h0[B_SZ * HIDD];
__device__ float g_scores[(S_LEN - 1) * B_SZ];
__device__ float g_attn[(S_LEN - 1) * B_SZ];
__device__ float g_attout[B_SZ * HIDD];
__device__ unsigned g_bar_cnt;
__device__ volatile unsigned g_bar_gen;

__global__ void init_kernel() {
    int i = blockIdx.x * blockDim.x + threadIdx.x;
    if (i < B_SZ * HIDD) g_h0[i] = 0.f;
    if (i == 0) { g_bar_cnt = 0u; *(unsigned*)&g_bar_gen = 0u; }
}

// ---- K1: gates  G[(t*64+b)][j] = emb[X[b,t]] . W_ih[j] + b_ih[j] + b_hh[j] ----
__global__ void __launch_bounds__(256) gates_kernel(const int* __restrict__ X,
                                                    const float* __restrict__ emb,
                                                    const float* __restrict__ W_ih,
                                                    const float* __restrict__ b_ih,
                                                    const float* __restrict__ b_hh) {
    __shared__ float2 As2[16 * 64];
    __shared__ float  Bs[16 * 68];
    __shared__ int rowidx[64];
    const int n0 = blockIdx.x * 64;
    const int m0 = blockIdx.y * 64;
    const int tid = threadIdx.x;

    if (tid < 64) {
        int m = m0 + tid;
        int t = m >> 6, b = m & 63;
        rowidx[tid] = X[b * S_LEN + t];
    }
    __syncthreads();

    const int tx = tid & 15, ty = tid >> 4;
    unsigned long long acc[4][2];
#pragma unroll
    for (int i = 0; i < 4; i++) { acc[i][0] = 0ull; acc[i][1] = 0ull; }

    const int lm = tid >> 2;
    const int lk = (tid & 3) * 4;

    for (int k0 = 0; k0 < EMBD; k0 += 16) {
        float4 av = *(const float4*)&emb[(size_t)rowidx[lm] * EMBD + k0 + lk];
        As2[(lk + 0) * 64 + lm] = make_float2(av.x, av.x);
        As2[(lk + 1) * 64 + lm] = make_float2(av.y, av.y);
        As2[(lk + 2) * 64 + lm] = make_float2(av.z, av.z);
        As2[(lk + 3) * 64 + lm] = make_float2(av.w, av.w);
        float4 bv = *(const float4*)&W_ih[(size_t)(n0 + lm) * EMBD + k0 + lk];
        Bs[(lk + 0) * 68 + lm] = bv.x; Bs[(lk + 1) * 68 + lm] = bv.y;
        Bs[(lk + 2) * 68 + lm] = bv.z; Bs[(lk + 3) * 68 + lm] = bv.w;
        __syncthreads();
#pragma unroll
        for (int kk = 0; kk < 16; kk++) {
            ulonglong2 a01 = *(const ulonglong2*)&As2[kk * 64 + ty * 4];
            ulonglong2 a23 = *(const ulonglong2*)&As2[kk * 64 + ty * 4 + 2];
            ulonglong2 bp  = *(const ulonglong2*)&Bs[kk * 68 + tx * 4];
            FFMA2(acc[0][0], a01.x, bp.x); FFMA2(acc[0][1], a01.x, bp.y);
            FFMA2(acc[1][0], a01.y, bp.x); FFMA2(acc[1][1], a01.y, bp.y);
            FFMA2(acc[2][0], a23.x, bp.x); FFMA2(acc[2][1], a23.x, bp.y);
            FFMA2(acc[3][0], a23.y, bp.x); FFMA2(acc[3][1], a23.y, bp.y);
        }
        __syncthreads();
    }
    float4 bi = *(const float4*)&b_ih[n0 + tx * 4];
    float4 bh = *(const float4*)&b_hh[n0 + tx * 4];
    float bias[4] = {bi.x + bh.x, bi.y + bh.y, bi.z + bh.z, bi.w + bh.w};
#pragma unroll
    for (int i = 0; i < 4; i++) {
        int m = m0 + ty * 4 + i;
        F2U p0, p1; p0.u = acc[i][0]; p1.u = acc[i][1];
        float4 o = make_float4(p0.f.x + bias[0], p0.f.y + bias[1],
                               p1.f.x + bias[2], p1.f.y + bias[3]);
        *(float4*)&g_G[(size_t)m * HIDD + n0 + tx * 4] = o;
    }
}

// ---- flat grid barrier (R3-proven) ----
__device__ __forceinline__ void grid_bar(unsigned target) {
    __threadfence();
    __syncthreads();
    if (threadIdx.x == 0) {
        unsigned a = atomicAdd(&g_bar_cnt, 1u);
        if (a == (unsigned)(RNN_NCTA - 1)) {
            atomicExch(&g_bar_cnt, 0u);
            __threadfence();
            atomicAdd((unsigned*)&g_bar_gen, 1u);
        } else {
            while (*(volatile unsigned*)&g_bar_gen < target) __nanosleep(32);
        }
        __threadfence();
    }
    __syncthreads();
}

// ---- K2: persistent recurrence, K-split 8, tile 8b x 4j, W pre-dup in SMEM ----
// CTA c: jg = c & 15 (64 j-cols), ks = c >> 4 (128 k each).
__global__ void __launch_bounds__(128, 1) rnn_kernel(const float* __restrict__ W_hh) {
    extern __shared__ char smem_raw[];
    float* hshf = (float*)smem_raw;                    // [128k][64b] undup
    float* Wd   = (float*)(smem_raw + 128 * 64 * 4);   // [128k][128] dup pairs: Wd[k][2j]=(w,w)
    const int tid = threadIdx.x;
    const int c = blockIdx.x;
    const int jg = c & 15;   // 64 j-cols per group
    const int ks = c >> 4;   // 128 K each

    // resident W slice, k-major, duplicated: Wd[k*128 + 2*jl] = Wd[..+1] = W_hh[jg*64+jl][ks*128+k]
    {
        int jl = tid & 63;
        int kc = (tid >> 6) * 64;
        const float* wr = &W_hh[(size_t)(jg * 64 + jl) * HIDD + ks * 128 + kc];
#pragma unroll
        for (int q = 0; q < 16; q++) {
            float4 wv = *(const float4*)&wr[q * 4];
            *(float2*)&Wd[(kc + q * 4 + 0) * 128 + 2 * jl] = make_float2(wv.x, wv.x);
            *(float2*)&Wd[(kc + q * 4 + 1) * 128 + 2 * jl] = make_float2(wv.y, wv.y);
            *(float2*)&Wd[(kc + q * 4 + 2) * 128 + 2 * jl] = make_float2(wv.z, wv.z);
            *(float2*)&Wd[(kc + q * 4 + 3) * 128 + 2 * jl] = make_float2(wv.w, wv.w);
        }
    }
    __syncthreads();

    const int b0  = (tid & 7) * 8;    // 8 b's per thread
    const int jl0 = (tid >> 3) * 4;   // 4 j's per thread (local)
    const int sb  = tid & 63;         // staging batch
    const int skc = (tid >> 6) * 64;  // staging k-chunk
    unsigned tgt = 0;

    for (int t = 0; t < S_LEN; ++t) {
        const float* hprev = (t == 0) ? g_h0 : (g_OUT + (size_t)(t - 1) * B_SZ * HIDD);
        // stage h transposed, undup: hshf[k*64+b] = h[b][k]
        {
            const float* hr = &hprev[(size_t)sb * HIDD + ks * 128 + skc];
#pragma unroll
            for (int q = 0; q < 16; q++) {
                float4 hv = __ldcg((const float4*)&hr[q * 4]);
                hshf[(skc + q * 4 + 0) * 64 + sb] = hv.x;
                hshf[(skc + q * 4 + 1) * 64 + sb] = hv.y;
                hshf[(skc + q * 4 + 2) * 64 + sb] = hv.z;
                hshf[(skc + q * 4 + 3) * 64 + sb] = hv.w;
            }
        }
        __syncthreads();

        unsigned long long acc[4][4];   // acc[j][bp], bp = b-pair index
#pragma unroll
        for (int i = 0; i < 4; i++)
#pragma unroll
            for (int p = 0; p < 4; p++) acc[i][p] = 0ull;

#pragma unroll 8
        for (int kk = 0; kk < 128; kk++) {
            ulonglong2 hA = *(const ulonglong2*)&hshf[kk * 64 + b0];      // (b0,b1),(b2,b3)
            ulonglong2 hB = *(const ulonglong2*)&hshf[kk * 64 + b0 + 4];  // (b4,b5),(b6,b7)
            ulonglong2 w01 = *(const ulonglong2*)&Wd[kk * 128 + 2 * jl0];     // dup(j0), dup(j1)
            ulonglong2 w23 = *(const ulonglong2*)&Wd[kk * 128 + 2 * jl0 + 4]; // dup(j2), dup(j3)
            FFMA2(acc[0][0], hA.x, w01.x); FFMA2(acc[0][1], hA.y, w01.x);
            FFMA2(acc[0][2], hB.x, w01.x); FFMA2(acc[0][3], hB.y, w01.x);
            FFMA2(acc[1][0], hA.x, w01.y); FFMA2(acc[1][1], hA.y, w01.y);
            FFMA2(acc[1][2], hB.x, w01.y); FFMA2(acc[1][3], hB.y, w01.y);
            FFMA2(acc[2][0], hA.x, w23.x); FFMA2(acc[2][1], hA.y, w23.x);
            FFMA2(acc[2][2], hB.x, w23.x); FFMA2(acc[2][3], hB.y, w23.x);
            FFMA2(acc[3][0], hA.x, w23.y); FFMA2(acc[3][1], hA.y, w23.y);
            FFMA2(acc[3][2], hB.x, w23.y); FFMA2(acc[3][3], hB.y, w23.y);
        }

        // write partials: g_P[ks][b][jg*64 + jl0 .. +3]
#pragma unroll
        for (int p = 0; p < 4; p++) {
            F2U a0, a1, a2, a3;
            a0.u = acc[0][p]; a1.u = acc[1][p]; a2.u = acc[2][p]; a3.u = acc[3][p];
            float4 lo = make_float4(a0.f.x, a1.f.x, a2.f.x, a3.f.x);
            float4 hi = make_float4(a0.f.y, a1.f.y, a2.f.y, a3.f.y);
            *(float4*)&g_P[ks * (B_SZ * HIDD) + (b0 + 2 * p) * HIDD + jg * 64 + jl0] = lo;
            *(float4*)&g_P[ks * (B_SZ * HIDD) + (b0 + 2 * p + 1) * HIDD + jg * 64 + jl0] = hi;
        }
        grid_bar(++tgt);

        // combine: 512 contiguous elements per CTA, sum 8 partials
        {
            int base = c * 512 + tid * 4;
            float4 s = __ldcg((const float4*)&g_P[base]);
#pragma unroll
            for (int sp = 1; sp < RNN_KS; sp++) {
                float4 p = __ldcg((const float4*)&g_P[sp * (B_SZ * HIDD) + base]);
                s.x += p.x; s.y += p.y; s.z += p.z; s.w += p.w;
            }
            float4 g = __ldcg((const float4*)&g_G[(size_t)t * B_SZ * HIDD + base]);
            float4 o;
            o.x = tanhf(g.x + s.x);
            o.y = tanhf(g.y + s.y);
            o.z = tanhf(g.z + s.z);
            o.w = tanhf(g.w + s.w);
            *(float4*)&g_OUT[(size_t)t * B_SZ * HIDD + base] = o;
        }
        grid_bar(++tgt);
    }
}

// ---- K3a: scores ----
__global__ void __launch_bounds__(256) scores_kernel() {
    const int s = blockIdx.x;
    const int w = threadIdx.x >> 5, lane = threadIdx.x & 31;
    const float* Pv = g_OUT + (size_t)s * B_SZ * HIDD;
    const float* Lv = g_OUT + (size_t)(S_LEN - 1) * B_SZ * HIDD;
#pragma unroll
    for (int i = 0; i < 8; i++) {
        int b = w * 8 + i;
        const float* p = Pv + (size_t)b * HIDD;
        const float* l = Lv + (size_t)b * HIDD;
        float acc = 0.f;
#pragma unroll 4
        for (int k = lane; k < HIDD; k += 32) acc += p[k] * l[k];
#pragma unroll
        for (int o = 16; o > 0; o >>= 1) acc += __shfl_down_sync(0xffffffffu, acc, o);
        if (lane == 0) g_scores[s * B_SZ + b] = acc;
    }
}

// ---- K3b: softmax over s per b ----
__global__ void __launch_bounds__(512) softmax_kernel() {
    const int b = blockIdx.x;
    const int tid = threadIdx.x;
    __shared__ float red[512];
    float v = (tid < S_LEN - 1) ? g_scores[tid * B_SZ + b] : -1e30f;
    red[tid] = v;
    __syncthreads();
    for (int s = 256; s > 0; s >>= 1) {
        if (tid < s) red[tid] = fmaxf(red[tid], red[tid + s]);
        __syncthreads();
    }
    float m = red[0];
    __syncthreads();
    float e = (tid < S_LEN - 1) ? expf(v - m) : 0.f;
    red[tid] = e;
    __syncthreads();
    for (int s = 256; s > 0; s >>= 1) {
        if (tid < s) red[tid] += red[tid + s];
        __syncthreads();
    }
    float inv = 1.f / red[0];
    if (tid < S_LEN - 1) g_attn[tid * B_SZ + b] = e * inv;
}

// ---- K3c: att_out ----
__global__ void __launch_bounds__(256) attout_kernel() {
    const int b = blockIdx.y;
    const int h = blockIdx.x * 256 + threadIdx.x;
    float acc = 0.f;
#pragma unroll 4
    for (int s = 0; s < S_LEN - 1; s++)
        acc += g_attn[s * B_SZ + b] * g_OUT[(size_t)s * B_SZ * HIDD + (size_t)b * HIDD + h];
    g_attout[b * HIDD + h] = acc;
}

// ---- K4: out GEMM ----
__global__ void __launch_bounds__(256) out_gemm_kernel(const float* __restrict__ W_out,
                                                       const float* __restrict__ b_out,
                                                       float* __restrict__ out) {
    __shared__ float2 Fs2[16 * 64];
    __shared__ float  Ws[16 * 132];
    const int n0 = blockIdx.x * 128;
    const int tid = threadIdx.x;
    const int tx = tid & 31, ty = tid >> 5;
    const float* last = g_OUT + (size_t)(S_LEN - 1) * B_SZ * HIDD;

    unsigned long long acc[8][2];
#pragma unroll
    for (int i = 0; i < 8; i++) { acc[i][0] = 0ull; acc[i][1] = 0ull; }

    const int mm = tid >> 2;
    const int kq = (tid & 3) * 4;

    for (int k0 = 0; k0 < FEATD; k0 += 16) {
        int k = k0 + kq;
        const float* src = (k < HIDD) ? &g_attout[mm * HIDD + k]
                                      : &last[(size_t)mm * HIDD + (k - HIDD)];
        float4 fv = *(const float4*)src;
        Fs2[(kq + 0) * 64 + mm] = make_float2(fv.x, fv.x);
        Fs2[(kq + 1) * 64 + mm] = make_float2(fv.y, fv.y);
        Fs2[(kq + 2) * 64 + mm] = make_float2(fv.z, fv.z);
        Fs2[(kq + 3) * 64 + mm] = make_float2(fv.w, fv.w);
#pragma unroll
        for (int r = 0; r < 2; r++) {
            int f = tid + r * 256;
            int nn = f >> 2;
            int kq2 = (f & 3) * 4;
            float4 wv = *(const float4*)&W_out[(size_t)(n0 + nn) * FEATD + k0 + kq2];
            Ws[(kq2 + 0) * 132 + nn] = wv.x; Ws[(kq2 + 1) * 132 + nn] = wv.y;
            Ws[(kq2 + 2) * 132 + nn] = wv.z; Ws[(kq2 + 3) * 132 + nn] = wv.w;
        }
        __syncthreads();
#pragma unroll
        for (int kk = 0; kk < 16; kk++) {
            ulonglong2 a01 = *(const ulonglong2*)&Fs2[kk * 64 + ty * 8];
            ulonglong2 a23 = *(const ulonglong2*)&Fs2[kk * 64 + ty * 8 + 2];
            ulonglong2 a45 = *(const ulonglong2*)&Fs2[kk * 64 + ty * 8 + 4];
            ulonglong2 a67 = *(const ulonglong2*)&Fs2[kk * 64 + ty * 8 + 6];
            ulonglong2 wp  = *(const ulonglong2*)&Ws[kk * 132 + tx * 4];
            FFMA2(acc[0][0], a01.x, wp.x); FFMA2(acc[0][1], a01.x, wp.y);
            FFMA2(acc[1][0], a01.y, wp.x); FFMA2(acc[1][1], a01.y, wp.y);
            FFMA2(acc[2][0], a23.x, wp.x); FFMA2(acc[2][1], a23.x, wp.y);
            FFMA2(acc[3][0], a23.y, wp.x); FFMA2(acc[3][1], a23.y, wp.y);
            FFMA2(acc[4][0], a45.x, wp.x); FFMA2(acc[4][1], a45.x, wp.y);
            FFMA2(acc[5][0], a45.y, wp.x); FFMA2(acc[5][1], a45.y, wp.y);
            FFMA2(acc[6][0], a67.x, wp.x); FFMA2(acc[6][1], a67.x, wp.y);
            FFMA2(acc[7][0], a67.y, wp.x); FFMA2(acc[7][1], a67.y, wp.y);
        }
        __syncthreads();
    }
    float4 bo = *(const float4*)&b_out[n0 + tx * 4];
#pragma unroll
    for (int i = 0; i < 8; i++) {
        int m = ty * 8 + i;
        F2U p0, p1; p0.u = acc[i][0]; p1.u = acc[i][1];
        float4 o = make_float4(p0.f.x + bo.x, p0.f.y + bo.y,
                               p1.f.x + bo.z, p1.f.y + bo.w);
        *(float4*)&out[(size_t)m * NCLS + n0 + tx * 4] = o;
    }
}

// ---- launch ----
extern "C" void kernel_launch(void* const* d_in, const int* in_sizes, int n_in,
                              void* d_out, int out_size) {
    (void)in_sizes; (void)n_in; (void)out_size;
    const int*   X     = (const int*)d_in[0];
    const float* emb   = (const float*)d_in[1];
    const float* W_ih  = (const float*)d_in[2];
    const float* W_hh  = (const float*)d_in[3];
    const float* b_ih  = (const float*)d_in[4];
    const float* b_hh  = (const float*)d_in[5];
    const float* W_out = (const float*)d_in[6];
    const float* b_out = (const float*)d_in[7];
    float* out = (float*)d_out;

    static bool attr_set = false;
    if (!attr_set) {
        cudaFuncSetAttribute(rnn_kernel, cudaFuncAttributeMaxDynamicSharedMemorySize, RNN_SMEM);
        attr_set = true;
    }

    init_kernel<<<256, 256>>>();
    gates_kernel<<<dim3(HIDD / 64, (S_LEN * B_SZ) / 64), 256>>>(X, emb, W_ih, b_ih, b_hh);
    rnn_kernel<<<RNN_NCTA, 128, RNN_SMEM>>>(W_hh);
    scores_kernel<<<S_LEN - 1, 256>>>();
    softmax_kernel<<<B_SZ, 512>>>();
    attout_kernel<<<dim3(HIDD / 256, B_SZ), 256>>>();
    out_gemm_kernel<<<NCLS / 128, 256>>>(W_out, b_out, out);
}